// round 10
// baseline (speedup 1.0000x reference)
#include <cuda_runtime.h>
#include <cuda_fp16.h>
#include <cuda_fp8.h>
#include <cstddef>
#include <cstdint>

#define N_A   100000
#define N_P   150000
#define N_TOT (N_A + N_P)
#define D     128
#define C_OUT 16
#define EMAX  2000000
#define HSCALE 32.0f

// -------------------- device scratch (no allocs allowed) --------------------
__device__ uint2 g_x16  [(size_t)N_TOT * 32];  // fp16x4 x plane
__device__ uint2 g_res16[(size_t)N_TOT * 32];  // fp16x4 res1 plane
__device__ uint2 g_hA16 [(size_t)N_A  * 32];   // fp16 hop-1 output (own-term plane)
__device__ uint2 g_hP16 [(size_t)N_P  * 32];
__device__ uint32_t g_hA8[(size_t)N_A * 32];   // fp8 e4m3 x HSCALE (hop-2 gather plane)
__device__ uint32_t g_hP8[(size_t)N_P * 32];
__device__ float g_W0c [D * D];
__device__ float g_W1c [D * D];
// CSR scratch (cnt zeroed by scatter2 each run; zero-init covers run #1)
__device__ int   g_cntA[N_A],     g_cntP[N_P];
__device__ int   g_rpA [N_A + 1], g_rpP [N_P + 1];
__device__ int   g_offA[N_A],     g_offP[N_P];
__device__ __align__(16) uint2 g_ecvA[EMAX];   // (col_local, val bits)
__device__ __align__(16) uint2 g_ecvP[EMAX];

// ----------------------------- fp16 / fp8 helpers ---------------------------
__device__ __forceinline__ float4 ldg_f16x4(const uint2* p) {
    uint2 r = __ldg(p);
    float2 a = __half22float2(*reinterpret_cast<const __half2*>(&r.x));
    float2 b = __half22float2(*reinterpret_cast<const __half2*>(&r.y));
    return make_float4(a.x, a.y, b.x, b.y);
}
__device__ __forceinline__ uint2 pack_f16x4(float4 v) {
    __half2 a = __floats2half2_rn(v.x, v.y);
    __half2 b = __floats2half2_rn(v.z, v.w);
    uint2 r;
    r.x = *reinterpret_cast<const uint32_t*>(&a);
    r.y = *reinterpret_cast<const uint32_t*>(&b);
    return r;
}
__device__ __forceinline__ uint32_t pack_fp8x4(float4 v) {   // v pre-scaled
    __nv_fp8x2_storage_t lo = __nv_cvt_float2_to_fp8x2(make_float2(v.x, v.y),
                                                       __NV_SATFINITE, __NV_E4M3);
    __nv_fp8x2_storage_t hi = __nv_cvt_float2_to_fp8x2(make_float2(v.z, v.w),
                                                       __NV_SATFINITE, __NV_E4M3);
    return (uint32_t)lo | ((uint32_t)hi << 16);
}
__device__ __forceinline__ float4 fp8x4_to_float4(uint32_t u) {
    __half2_raw lo = __nv_cvt_fp8x2_to_halfraw2((__nv_fp8x2_storage_t)(u & 0xffffu), __NV_E4M3);
    __half2_raw hi = __nv_cvt_fp8x2_to_halfraw2((__nv_fp8x2_storage_t)(u >> 16),     __NV_E4M3);
    float2 a = __half22float2(*reinterpret_cast<const __half2*>(&lo));
    float2 b = __half22float2(*reinterpret_cast<const __half2*>(&hi));
    return make_float4(a.x, a.y, b.x, b.y);
}
__device__ __forceinline__ void accum16(float4& a, uint2 h, float v) {
    float2 f0 = __half22float2(*reinterpret_cast<const __half2*>(&h.x));
    float2 f1 = __half22float2(*reinterpret_cast<const __half2*>(&h.y));
    a.x += v * f0.x; a.y += v * f0.y; a.z += v * f1.x; a.w += v * f1.y;
}
__device__ __forceinline__ void accum8f(float4& a, uint32_t h, float v) {
    float4 f = fp8x4_to_float4(h);
    a.x += v * f.x; a.y += v * f.y; a.z += v * f.z; a.w += v * f.w;
}

// ------------------------- gather loops (MLP=4, prefetched) ------------------
__device__ __forceinline__ float4 gather16(
    const uint2* __restrict__ ecv, const uint2* __restrict__ src,
    int s, int e, int lane) {
    float4 a0 = {0, 0, 0, 0}, a1 = {0, 0, 0, 0};
    int i = s;
    if ((i & 1) && i < e) {
        uint2 p = __ldg(&ecv[i]);
        accum16(a0, __ldg(src + (size_t)p.x * 32 + lane), __uint_as_float(p.y));
        i++;
    }
    if (i + 4 <= e) {
        uint4 eAB = __ldg((const uint4*)(ecv + i));
        uint4 eCD = __ldg((const uint4*)(ecv + i + 2));
        for (; i + 8 <= e; i += 4) {
            uint4 nAB = __ldg((const uint4*)(ecv + i + 4));
            uint4 nCD = __ldg((const uint4*)(ecv + i + 6));
            uint2 h0 = __ldg(src + (size_t)eAB.x * 32 + lane);
            uint2 h1 = __ldg(src + (size_t)eAB.z * 32 + lane);
            uint2 h2 = __ldg(src + (size_t)eCD.x * 32 + lane);
            uint2 h3 = __ldg(src + (size_t)eCD.z * 32 + lane);
            accum16(a0, h0, __uint_as_float(eAB.y));
            accum16(a1, h1, __uint_as_float(eAB.w));
            accum16(a0, h2, __uint_as_float(eCD.y));
            accum16(a1, h3, __uint_as_float(eCD.w));
            eAB = nAB; eCD = nCD;
        }
        uint2 h0 = __ldg(src + (size_t)eAB.x * 32 + lane);
        uint2 h1 = __ldg(src + (size_t)eAB.z * 32 + lane);
        uint2 h2 = __ldg(src + (size_t)eCD.x * 32 + lane);
        uint2 h3 = __ldg(src + (size_t)eCD.z * 32 + lane);
        accum16(a0, h0, __uint_as_float(eAB.y));
        accum16(a1, h1, __uint_as_float(eAB.w));
        accum16(a0, h2, __uint_as_float(eCD.y));
        accum16(a1, h3, __uint_as_float(eCD.w));
        i += 4;
    }
    for (; i < e; i++) {
        uint2 p = __ldg(&ecv[i]);
        accum16(a0, __ldg(src + (size_t)p.x * 32 + lane), __uint_as_float(p.y));
    }
    a0.x += a1.x; a0.y += a1.y; a0.z += a1.z; a0.w += a1.w;
    return a0;
}

__device__ __forceinline__ float4 gather8(
    const uint2* __restrict__ ecv, const uint32_t* __restrict__ src,
    int s, int e, int lane) {
    float4 a0 = {0, 0, 0, 0}, a1 = {0, 0, 0, 0};
    int i = s;
    if ((i & 1) && i < e) {
        uint2 p = __ldg(&ecv[i]);
        accum8f(a0, __ldg(src + (size_t)p.x * 32 + lane), __uint_as_float(p.y));
        i++;
    }
    if (i + 4 <= e) {
        uint4 eAB = __ldg((const uint4*)(ecv + i));
        uint4 eCD = __ldg((const uint4*)(ecv + i + 2));
        for (; i + 8 <= e; i += 4) {
            uint4 nAB = __ldg((const uint4*)(ecv + i + 4));
            uint4 nCD = __ldg((const uint4*)(ecv + i + 6));
            uint32_t h0 = __ldg(src + (size_t)eAB.x * 32 + lane);
            uint32_t h1 = __ldg(src + (size_t)eAB.z * 32 + lane);
            uint32_t h2 = __ldg(src + (size_t)eCD.x * 32 + lane);
            uint32_t h3 = __ldg(src + (size_t)eCD.z * 32 + lane);
            accum8f(a0, h0, __uint_as_float(eAB.y));
            accum8f(a1, h1, __uint_as_float(eAB.w));
            accum8f(a0, h2, __uint_as_float(eCD.y));
            accum8f(a1, h3, __uint_as_float(eCD.w));
            eAB = nAB; eCD = nCD;
        }
        uint32_t h0 = __ldg(src + (size_t)eAB.x * 32 + lane);
        uint32_t h1 = __ldg(src + (size_t)eAB.z * 32 + lane);
        uint32_t h2 = __ldg(src + (size_t)eCD.x * 32 + lane);
        uint32_t h3 = __ldg(src + (size_t)eCD.z * 32 + lane);
        accum8f(a0, h0, __uint_as_float(eAB.y));
        accum8f(a1, h1, __uint_as_float(eAB.w));
        accum8f(a0, h2, __uint_as_float(eCD.y));
        accum8f(a1, h3, __uint_as_float(eCD.w));
        i += 4;
    }
    for (; i < e; i++) {
        uint2 p = __ldg(&ecv[i]);
        accum8f(a0, __ldg(src + (size_t)p.x * 32 + lane), __uint_as_float(p.y));
    }
    a0.x += a1.x; a0.y += a1.y; a0.z += a1.z; a0.w += a1.w;
    return a0;
}

// -------------------- Wc = Wp @ W1 (both weights, one launch) ----------------
__global__ void __launch_bounds__(128) wcomb2_kernel(
    const float* __restrict__ Wp0, const float* __restrict__ Wp1,
    const float* __restrict__ W1,
    float* __restrict__ Wc0, float* __restrict__ Wc1) {
    __shared__ float srow[D];
    const float* Wp = (blockIdx.x < 128) ? Wp0 : Wp1;
    float*       Wc = (blockIdx.x < 128) ? Wc0 : Wc1;
    int r = blockIdx.x & 127;
    srow[threadIdx.x] = Wp[r * D + threadIdx.x];
    __syncthreads();
    float acc = 0.f;
    #pragma unroll 8
    for (int k = 0; k < D; k++)
        acc += srow[k] * __ldg(&W1[k * D + threadIdx.x]);
    Wc[r * D + threadIdx.x] = acc;
}

// ------------- fused projection GEMM + bias + relu + row-normalize ----------
__global__ void __launch_bounds__(256) proj_norm_kernel(
    const float* __restrict__ x0, const float* __restrict__ x1,
    const float* __restrict__ Wc0, const float* __restrict__ Wc1,
    const float* __restrict__ bias, uint2* __restrict__ xout16) {
    __shared__ float sA[64][128];
    __shared__ float sB[32][128];

    const int nblkA = (N_A + 63) / 64;
    const float* xin;
    const float* Wc;
    int row0, nrows, base_out;
    if ((int)blockIdx.x < nblkA) {
        xin = x0; Wc = Wc0; row0 = blockIdx.x * 64; nrows = N_A; base_out = 0;
    } else {
        xin = x1; Wc = Wc1; row0 = (blockIdx.x - nblkA) * 64; nrows = N_P; base_out = N_A;
    }
    const int tid = threadIdx.x;

    #pragma unroll
    for (int i = 0; i < 8; i++) {
        int idx = tid + i * 256;
        int r   = idx >> 5;
        int k4  = idx & 31;
        float4 v = make_float4(0.f, 0.f, 0.f, 0.f);
        if (row0 + r < nrows)
            v = __ldg((const float4*)(xin + (size_t)(row0 + r) * D) + k4);
        *(float4*)&sA[r][k4 * 4] = v;
    }

    const int tr = tid >> 5;
    const int tc = tid & 31;
    float acc[8][4];
    #pragma unroll
    for (int i = 0; i < 8; i++)
        #pragma unroll
        for (int j = 0; j < 4; j++) acc[i][j] = 0.f;

    for (int kc = 0; kc < 4; kc++) {
        __syncthreads();
        #pragma unroll
        for (int i = 0; i < 4; i++) {
            int idx = tid + i * 256;
            int kk  = idx >> 5;
            int c4  = idx & 31;
            *(float4*)&sB[kk][c4 * 4] =
                __ldg((const float4*)(Wc + (size_t)(kc * 32 + kk) * D) + c4);
        }
        __syncthreads();
        #pragma unroll
        for (int kk = 0; kk < 32; kk++) {
            float4 bv = *(float4*)&sB[kk][tc * 4];
            #pragma unroll
            for (int i = 0; i < 8; i++) {
                float a = sA[tr * 8 + i][kc * 32 + kk];
                acc[i][0] += a * bv.x; acc[i][1] += a * bv.y;
                acc[i][2] += a * bv.z; acc[i][3] += a * bv.w;
            }
        }
    }

    float4 bv = __ldg((const float4*)bias + tc);
    float bb[4] = {bv.x, bv.y, bv.z, bv.w};
    #pragma unroll
    for (int i = 0; i < 8; i++)
        #pragma unroll
        for (int j = 0; j < 4; j++) {
            float v = acc[i][j] + bb[j];
            acc[i][j] = v > 0.f ? v : 0.f;
        }

    #pragma unroll
    for (int i = 0; i < 8; i++) {
        float s = acc[i][0] + acc[i][1] + acc[i][2] + acc[i][3];
        float q = acc[i][0]*acc[i][0] + acc[i][1]*acc[i][1]
                + acc[i][2]*acc[i][2] + acc[i][3]*acc[i][3];
        #pragma unroll
        for (int o = 16; o; o >>= 1) {
            s += __shfl_xor_sync(0xffffffffu, s, o);
            q += __shfl_xor_sync(0xffffffffu, q, o);
        }
        float mean = s * (1.f / 128.f);
        float var  = (q - 128.f * mean * mean) * (1.f / 127.f);
        float rstd = (var > 0.f) ? rsqrtf(var) : 0.f;
        int r = row0 + tr * 8 + i;
        if (r < nrows) {
            size_t R = (size_t)(base_out + r);
            float4 o;
            o.x = (acc[i][0] - mean) * rstd;
            o.y = (acc[i][1] - mean) * rstd;
            o.z = (acc[i][2] - mean) * rstd;
            o.w = (acc[i][3] - mean) * rstd;
            xout16[R * 32 + tc] = pack_f16x4(o);
        }
    }
}

// ------------------------------ CSR build -----------------------------------
__global__ void __launch_bounds__(256) hist2_kernel(
    const int* __restrict__ rowsA, int E1, int* __restrict__ cntA,
    const int* __restrict__ rowsP, int E2, int* __restrict__ cntP) {
    int i = blockIdx.x * 256 + threadIdx.x;
    if (i < E1) atomicAdd(&cntA[__ldg(&rowsA[i])], 1);
    if (i < E2) atomicAdd(&cntP[__ldg(&rowsP[i]) - N_A], 1);
}

// Single-launch sync-free scan: each block redundantly sums all preceding
// cnt chunks (coalesced, L2-resident) -> no flags, no second pass.
__global__ void __launch_bounds__(256) scan_one_kernel(
    const int* __restrict__ cntA, int nA, int* __restrict__ rpA, int* __restrict__ offsA, int nbA,
    const int* __restrict__ cntP, int nP, int* __restrict__ rpP, int* __restrict__ offsP, int nbP) {
    __shared__ int wsum[8];
    __shared__ int s_boff;
    const int* cnt; int n; int* rp; int* offs; int blk; int nb;
    if ((int)blockIdx.x < nbA) {
        cnt = cntA; n = nA; rp = rpA; offs = offsA; blk = blockIdx.x; nb = nbA;
    } else {
        cnt = cntP; n = nP; rp = rpP; offs = offsP; blk = blockIdx.x - nbA; nb = nbP;
    }
    const int base = blk * 2048;
    const int t = threadIdx.x;
    const int lane = t & 31, w = t >> 5;

    // ---- block offset: sum cnt[0..base) ----
    int pre = 0;
    for (int j = t; j < base; j += 256) pre += __ldg(&cnt[j]);
    #pragma unroll
    for (int o = 16; o; o >>= 1) pre += __shfl_xor_sync(0xffffffffu, pre, o);
    if (lane == 0) wsum[w] = pre;
    __syncthreads();
    if (t == 0) {
        int b = 0;
        #pragma unroll
        for (int k = 0; k < 8; k++) b += wsum[k];
        s_boff = b;
    }
    __syncthreads();
    const int boff = s_boff;
    __syncthreads();   // wsum reused below

    // ---- local scan of this chunk ----
    int v[8]; int s = 0;
    #pragma unroll
    for (int i = 0; i < 8; i++) {
        int idx = base + t * 8 + i;
        int c = (idx < n) ? __ldg(&cnt[idx]) : 0;
        v[i] = s; s += c;
    }
    int p = s;
    #pragma unroll
    for (int o = 1; o < 32; o <<= 1) {
        int q = __shfl_up_sync(0xffffffffu, p, o);
        if (lane >= o) p += q;
    }
    if (lane == 31) wsum[w] = p;
    __syncthreads();
    if (t < 8) {
        int ws = wsum[t];
        int pp = ws;
        #pragma unroll
        for (int o = 1; o < 8; o <<= 1) {
            int q = __shfl_up_sync(0xffu, pp, o);
            if (t >= o) pp += q;
        }
        wsum[t] = pp - ws;             // exclusive over warps
        if (t == 7 && blk == nb - 1)   // chunk total -> rp[n]
            rp[n] = boff + pp;
    }
    __syncthreads();
    int texcl = boff + (p - s) + wsum[w];
    #pragma unroll
    for (int i = 0; i < 8; i++) {
        int idx = base + t * 8 + i;
        if (idx < n) { rp[idx] = texcl + v[i]; offs[idx] = texcl + v[i]; }
    }
}

// scatter + zero cnt for the next graph replay
__global__ void __launch_bounds__(256) scatter2_kernel(
    const int* __restrict__ rowsA, const int* __restrict__ colsA,
    const float* __restrict__ valsA, int E1, int* __restrict__ offsA, uint2* __restrict__ ecvA,
    int* __restrict__ cntA,
    const int* __restrict__ rowsP, const int* __restrict__ colsP,
    const float* __restrict__ valsP, int E2, int* __restrict__ offsP, uint2* __restrict__ ecvP,
    int* __restrict__ cntP) {
    int i = blockIdx.x * 256 + threadIdx.x;
    if (i < N_A) cntA[i] = 0;
    if (i < N_P) cntP[i] = 0;
    if (i < E1) {
        int r = __ldg(&rowsA[i]);
        int pos = atomicAdd(&offsA[r], 1);
        ecvA[pos] = make_uint2((unsigned)(__ldg(&colsA[i]) - N_A), __float_as_uint(__ldg(&valsA[i])));
    }
    if (i < E2) {
        int r = __ldg(&rowsP[i]) - N_A;
        int pos = atomicAdd(&offsP[r], 1);
        ecvP[pos] = make_uint2((unsigned)__ldg(&colsP[i]), __float_as_uint(__ldg(&valsP[i])));
    }
}

// --------------------- merged hop-1 SpMM (A + P in one grid) -----------------
// gathers fp16 src; writes fp16 (own-term) + fp8 (gather) planes
__global__ void __launch_bounds__(256) spmm_hop1_kernel(
    const int* __restrict__ rpA, const uint2* __restrict__ ecvA,
    const uint2* __restrict__ srcA, uint2* __restrict__ dstA16, uint32_t* __restrict__ dstA8,
    const int* __restrict__ rpP, const uint2* __restrict__ ecvP,
    const uint2* __restrict__ srcP, uint2* __restrict__ dstP16, uint32_t* __restrict__ dstP8) {
    int g = (int)((blockIdx.x * 256u + threadIdx.x) >> 5);
    if (g >= N_TOT) return;
    int lane = threadIdx.x & 31;
    const int* rp; const uint2* ecv; const uint2* src; uint2* dst16; uint32_t* dst8; int r;
    if (g < N_A) { rp = rpA; ecv = ecvA; src = srcA; dst16 = dstA16; dst8 = dstA8; r = g; }
    else         { rp = rpP; ecv = ecvP; src = srcP; dst16 = dstP16; dst8 = dstP8; r = g - N_A; }
    int s = __ldg(&rp[r]), e = __ldg(&rp[r + 1]);
    float4 a = gather16(ecv, src, s, e, lane);
    dst16[(size_t)r * 32 + lane] = pack_f16x4(a);
    float4 as = make_float4(a.x * HSCALE, a.y * HSCALE, a.z * HSCALE, a.w * HSCALE);
    dst8[(size_t)r * 32 + lane] = pack_fp8x4(as);
}

// ------------- merged pass-1 hop-2 fused with combine (A + P) ---------------
// gathers fp8 h (hop-2); own-term read from fp16 plane
__global__ void __launch_bounds__(256) spmm_fused_kernel(
    const int* __restrict__ rpA, const uint2* __restrict__ ecvA,
    const int* __restrict__ rpP, const uint2* __restrict__ ecvP,
    const uint2* __restrict__ hA16, const uint2* __restrict__ hP16,
    const uint32_t* __restrict__ hA8, const uint32_t* __restrict__ hP8,
    const uint2* __restrict__ x16, uint2* __restrict__ res16,
    const float* __restrict__ coe) {
    int g = (int)((blockIdx.x * 256u + threadIdx.x) >> 5);
    if (g >= N_TOT) return;
    int lane = threadIdx.x & 31;
    const int* rp; const uint2* ecv; const uint32_t* hsrc8; const uint2* hown;
    int r, c_own, c_hop;
    if (g < N_A) { rp = rpA; ecv = ecvA; hsrc8 = hP8; hown = hA16; r = g;       c_own = 1; c_hop = 3; }
    else         { rp = rpP; ecv = ecvP; hsrc8 = hA8; hown = hP16; r = g - N_A; c_own = 2; c_hop = 4; }
    int s = __ldg(&rp[r]), e = __ldg(&rp[r + 1]);
    float4 w = gather8(ecv, hsrc8, s, e, lane);

    size_t R = (size_t)g;
    float c0 = __ldg(&coe[0]);
    float cw = __ldg(&coe[c_own]);
    float ch = __ldg(&coe[c_hop]) * (1.0f / HSCALE);
    float4 xv = ldg_f16x4(x16 + R * 32 + lane);
    float4 hv = ldg_f16x4(hown + (size_t)r * 32 + lane);
    float4 o;
    o.x = c0 * xv.x + cw * hv.x + ch * w.x;
    o.y = c0 * xv.y + cw * hv.y + ch * w.y;
    o.z = c0 * xv.z + cw * hv.z + ch * w.z;
    o.w = c0 * xv.w + cw * hv.w + ch * w.w;
    res16[R * 32 + lane] = pack_f16x4(o);
}

// ------ merged pass-2 hop-2 fused with combine AND output GEMM (A + P) -------
__global__ void __launch_bounds__(256) spmm_fused_out_kernel(
    const int* __restrict__ rpA, const uint2* __restrict__ ecvA,
    const int* __restrict__ rpP, const uint2* __restrict__ ecvP,
    const uint2* __restrict__ hA16, const uint2* __restrict__ hP16,
    const uint32_t* __restrict__ hA8, const uint32_t* __restrict__ hP8,
    const uint2* __restrict__ res16, float* __restrict__ out,
    const float* __restrict__ coe,
    const float* __restrict__ W2, const float* __restrict__ b2) {
    __shared__ float sW[C_OUT][D];
    __shared__ float sb2[C_OUT];
    int tid = threadIdx.x;
    for (int i = tid; i < C_OUT * D; i += 256) {
        int c = i >> 7, k = i & 127;
        sW[c][k] = __ldg(&W2[k * C_OUT + c]);
    }
    if (tid < C_OUT) sb2[tid] = __ldg(&b2[tid]);
    __syncthreads();

    int g = (int)((blockIdx.x * 256u + tid) >> 5);
    if (g >= N_TOT) return;
    int lane = tid & 31;
    const int* rp; const uint2* ecv; const uint32_t* hsrc8; const uint2* hown;
    int r, c_own, c_hop;
    if (g < N_A) { rp = rpA; ecv = ecvA; hsrc8 = hP8; hown = hA16; r = g;       c_own = 2; c_hop = 4; }
    else         { rp = rpP; ecv = ecvP; hsrc8 = hA8; hown = hP16; r = g - N_A; c_own = 1; c_hop = 3; }
    int s = __ldg(&rp[r]), e = __ldg(&rp[r + 1]);
    float4 w = gather8(ecv, hsrc8, s, e, lane);

    size_t R = (size_t)g;
    float c0 = __ldg(&coe[0]);
    float cw = __ldg(&coe[c_own]);
    float ch = __ldg(&coe[c_hop]) * (1.0f / HSCALE);
    float4 xv = ldg_f16x4(res16 + R * 32 + lane);
    float4 hv = ldg_f16x4(hown + (size_t)r * 32 + lane);
    float o0 = c0 * xv.x + cw * hv.x + ch * w.x;
    float o1 = c0 * xv.y + cw * hv.y + ch * w.y;
    float o2 = c0 * xv.z + cw * hv.z + ch * w.z;
    float o3 = c0 * xv.w + cw * hv.w + ch * w.w;

    float p[C_OUT];
    #pragma unroll
    for (int c = 0; c < C_OUT; c++) {
        float4 wv = *(const float4*)&sW[c][lane * 4];
        p[c] = o0 * wv.x + o1 * wv.y + o2 * wv.z + o3 * wv.w;
    }
    #pragma unroll
    for (int off = 16; off; off >>= 1) {
        #pragma unroll
        for (int c = 0; c < C_OUT; c++)
            p[c] += __shfl_xor_sync(0xffffffffu, p[c], off);
    }
    if (lane < C_OUT)
        out[R * C_OUT + lane] = p[lane] + sb2[lane];
}

// ----------------------------------- launch ---------------------------------
extern "C" void kernel_launch(void* const* d_in, const int* in_sizes, int n_in,
                              void* d_out, int out_size) {
    const float* x0      = (const float*)d_in[0];
    const float* x1      = (const float*)d_in[1];
    const float* vals_ap = (const float*)d_in[2];
    const float* vals_pa = (const float*)d_in[3];
    const int*   rows_ap = (const int*)  d_in[4];
    const int*   cols_ap = (const int*)  d_in[5];
    const int*   rows_pa = (const int*)  d_in[6];
    const int*   cols_pa = (const int*)  d_in[7];
    const float* Wp0     = (const float*)d_in[8];
    const float* Wp1     = (const float*)d_in[9];
    const float* W1      = (const float*)d_in[10];
    const float* b1      = (const float*)d_in[11];
    const float* W2      = (const float*)d_in[12];
    const float* b2      = (const float*)d_in[13];
    const float* coe     = (const float*)d_in[14];
    float* out = (float*)d_out;

    const int E1 = in_sizes[2];
    const int E2 = in_sizes[3];

    float *pW0c, *pW1c;
    uint2 *px16, *pres16, *phA16, *phP16, *pecvA, *pecvP;
    uint32_t *phA8, *phP8;
    int *pcntA, *pcntP, *prpA, *prpP, *poffA, *poffP;
    cudaGetSymbolAddress((void**)&px16,   g_x16);
    cudaGetSymbolAddress((void**)&pres16, g_res16);
    cudaGetSymbolAddress((void**)&phA16,  g_hA16);
    cudaGetSymbolAddress((void**)&phP16,  g_hP16);
    cudaGetSymbolAddress((void**)&phA8,   g_hA8);
    cudaGetSymbolAddress((void**)&phP8,   g_hP8);
    cudaGetSymbolAddress((void**)&pW0c,   g_W0c);
    cudaGetSymbolAddress((void**)&pW1c,   g_W1c);
    cudaGetSymbolAddress((void**)&pcntA,  g_cntA);
    cudaGetSymbolAddress((void**)&pcntP,  g_cntP);
    cudaGetSymbolAddress((void**)&prpA,   g_rpA);
    cudaGetSymbolAddress((void**)&prpP,   g_rpP);
    cudaGetSymbolAddress((void**)&poffA,  g_offA);
    cudaGetSymbolAddress((void**)&poffP,  g_offP);
    cudaGetSymbolAddress((void**)&pecvA,  g_ecvA);
    cudaGetSymbolAddress((void**)&pecvP,  g_ecvP);

    const int nbA = (N_A + 2047) / 2048;
    const int nbP = (N_P + 2047) / 2048;
    const int gT  = (int)(((size_t)N_TOT * 32 + 255) / 256);
    const int Emax = E1 > E2 ? E1 : E2;

    // 5 launches before the SpMM phase, so (6) spmm_hop1 lands in the
    // ncu capture slot (-s 5 -c 1).
    wcomb2_kernel<<<2 * D, D>>>(Wp0, Wp1, W1, pW0c, pW1c);
    proj_norm_kernel<<<(N_A + 63) / 64 + (N_P + 63) / 64, 256>>>(
        x0, x1, pW0c, pW1c, b1, px16);
    hist2_kernel<<<(Emax + 255) / 256, 256>>>(rows_ap, E1, pcntA, rows_pa, E2, pcntP);
    scan_one_kernel<<<nbA + nbP, 256>>>(pcntA, N_A, prpA, poffA, nbA,
                                        pcntP, N_P, prpP, poffP, nbP);
    scatter2_kernel<<<(Emax + 255) / 256, 256>>>(
        rows_ap, cols_ap, vals_ap, E1, poffA, pecvA, pcntA,
        rows_pa, cols_pa, vals_pa, E2, poffP, pecvP, pcntP);

    // ---------------- pass 1 (first_order = AP, PA) ----------------
    spmm_hop1_kernel<<<gT, 256>>>(prpA, pecvA, px16 + (size_t)N_A * 32, phA16, phA8,
                                  prpP, pecvP, px16,                    phP16, phP8);
    spmm_fused_kernel<<<gT, 256>>>(prpA, pecvA, prpP, pecvP,
                                   phA16, phP16, phA8, phP8,
                                   px16, pres16, coe);

    // ---------------- pass 2 (first_order = PA, AP) ----------------
    spmm_hop1_kernel<<<gT, 256>>>(prpA, pecvA, pres16 + (size_t)N_A * 32, phA16, phA8,
                                  prpP, pecvP, pres16,                    phP16, phP8);
    spmm_fused_out_kernel<<<gT, 256>>>(prpA, pecvA, prpP, pecvP,
                                       phA16, phP16, phA8, phP8,
                                       pres16, out, coe, W2, b2);
}

// round 11
// speedup vs baseline: 1.0190x; 1.0190x over previous
#include <cuda_runtime.h>
#include <cuda_fp16.h>
#include <cuda_fp8.h>
#include <cstddef>
#include <cstdint>

#define N_A   100000
#define N_P   150000
#define N_TOT (N_A + N_P)
#define D     128
#define C_OUT 16
#define EMAX  2000000
#define HSCALE 32.0f

// -------------------- device scratch (no allocs allowed) --------------------
__device__ uint2 g_x16  [(size_t)N_TOT * 32];  // fp16x4 x plane
__device__ uint2 g_res16[(size_t)N_TOT * 32];  // fp16x4 res1 plane
__device__ uint2 g_hA16 [(size_t)N_A  * 32];   // fp16 hop-1 output (own-term plane)
__device__ uint2 g_hP16 [(size_t)N_P  * 32];
__device__ uint32_t g_hA8[(size_t)N_A * 32];   // fp8 e4m3 x HSCALE (hop-2 gather plane)
__device__ uint32_t g_hP8[(size_t)N_P * 32];
__device__ float g_W0c [D * D];
__device__ float g_W1c [D * D];
// CSR scratch (cnt zeroed by scatter2 each run; zero-init covers run #1)
__device__ int   g_cntA[N_A],     g_cntP[N_P];
__device__ int   g_rpA [N_A + 1], g_rpP [N_P + 1];
__device__ int   g_offA[N_A],     g_offP[N_P];
__device__ int   g_bsumA[256],    g_bsumP[256];
__device__ __align__(16) uint2 g_ecvA[EMAX];   // (col_local, val bits)
__device__ __align__(16) uint2 g_ecvP[EMAX];

// ----------------------------- fp16 / fp8 helpers ---------------------------
__device__ __forceinline__ float4 ldg_f16x4(const uint2* p) {
    uint2 r = __ldg(p);
    float2 a = __half22float2(*reinterpret_cast<const __half2*>(&r.x));
    float2 b = __half22float2(*reinterpret_cast<const __half2*>(&r.y));
    return make_float4(a.x, a.y, b.x, b.y);
}
__device__ __forceinline__ uint2 pack_f16x4(float4 v) {
    __half2 a = __floats2half2_rn(v.x, v.y);
    __half2 b = __floats2half2_rn(v.z, v.w);
    uint2 r;
    r.x = *reinterpret_cast<const uint32_t*>(&a);
    r.y = *reinterpret_cast<const uint32_t*>(&b);
    return r;
}
__device__ __forceinline__ uint32_t pack_fp8x4(float4 v) {   // v pre-scaled
    __nv_fp8x2_storage_t lo = __nv_cvt_float2_to_fp8x2(make_float2(v.x, v.y),
                                                       __NV_SATFINITE, __NV_E4M3);
    __nv_fp8x2_storage_t hi = __nv_cvt_float2_to_fp8x2(make_float2(v.z, v.w),
                                                       __NV_SATFINITE, __NV_E4M3);
    return (uint32_t)lo | ((uint32_t)hi << 16);
}
__device__ __forceinline__ float4 fp8x4_to_float4(uint32_t u) {
    __half2_raw lo = __nv_cvt_fp8x2_to_halfraw2((__nv_fp8x2_storage_t)(u & 0xffffu), __NV_E4M3);
    __half2_raw hi = __nv_cvt_fp8x2_to_halfraw2((__nv_fp8x2_storage_t)(u >> 16),     __NV_E4M3);
    float2 a = __half22float2(*reinterpret_cast<const __half2*>(&lo));
    float2 b = __half22float2(*reinterpret_cast<const __half2*>(&hi));
    return make_float4(a.x, a.y, b.x, b.y);
}
__device__ __forceinline__ void accum16(float4& a, uint2 h, float v) {
    float2 f0 = __half22float2(*reinterpret_cast<const __half2*>(&h.x));
    float2 f1 = __half22float2(*reinterpret_cast<const __half2*>(&h.y));
    a.x += v * f0.x; a.y += v * f0.y; a.z += v * f1.x; a.w += v * f1.y;
}
__device__ __forceinline__ void accum8f(float4& a, uint32_t h, float v) {
    float4 f = fp8x4_to_float4(h);
    a.x += v * f.x; a.y += v * f.y; a.z += v * f.z; a.w += v * f.w;
}

// ------------------------- gather loops (MLP=4, prefetched) ------------------
__device__ __forceinline__ float4 gather16(
    const uint2* __restrict__ ecv, const uint2* __restrict__ src,
    int s, int e, int lane) {
    float4 a0 = {0, 0, 0, 0}, a1 = {0, 0, 0, 0};
    int i = s;
    if ((i & 1) && i < e) {
        uint2 p = __ldg(&ecv[i]);
        accum16(a0, __ldg(src + (size_t)p.x * 32 + lane), __uint_as_float(p.y));
        i++;
    }
    if (i + 4 <= e) {
        uint4 eAB = __ldg((const uint4*)(ecv + i));
        uint4 eCD = __ldg((const uint4*)(ecv + i + 2));
        for (; i + 8 <= e; i += 4) {
            uint4 nAB = __ldg((const uint4*)(ecv + i + 4));
            uint4 nCD = __ldg((const uint4*)(ecv + i + 6));
            uint2 h0 = __ldg(src + (size_t)eAB.x * 32 + lane);
            uint2 h1 = __ldg(src + (size_t)eAB.z * 32 + lane);
            uint2 h2 = __ldg(src + (size_t)eCD.x * 32 + lane);
            uint2 h3 = __ldg(src + (size_t)eCD.z * 32 + lane);
            accum16(a0, h0, __uint_as_float(eAB.y));
            accum16(a1, h1, __uint_as_float(eAB.w));
            accum16(a0, h2, __uint_as_float(eCD.y));
            accum16(a1, h3, __uint_as_float(eCD.w));
            eAB = nAB; eCD = nCD;
        }
        uint2 h0 = __ldg(src + (size_t)eAB.x * 32 + lane);
        uint2 h1 = __ldg(src + (size_t)eAB.z * 32 + lane);
        uint2 h2 = __ldg(src + (size_t)eCD.x * 32 + lane);
        uint2 h3 = __ldg(src + (size_t)eCD.z * 32 + lane);
        accum16(a0, h0, __uint_as_float(eAB.y));
        accum16(a1, h1, __uint_as_float(eAB.w));
        accum16(a0, h2, __uint_as_float(eCD.y));
        accum16(a1, h3, __uint_as_float(eCD.w));
        i += 4;
    }
    for (; i < e; i++) {
        uint2 p = __ldg(&ecv[i]);
        accum16(a0, __ldg(src + (size_t)p.x * 32 + lane), __uint_as_float(p.y));
    }
    a0.x += a1.x; a0.y += a1.y; a0.z += a1.z; a0.w += a1.w;
    return a0;
}

__device__ __forceinline__ float4 gather8(
    const uint2* __restrict__ ecv, const uint32_t* __restrict__ src,
    int s, int e, int lane) {
    float4 a0 = {0, 0, 0, 0}, a1 = {0, 0, 0, 0};
    int i = s;
    if ((i & 1) && i < e) {
        uint2 p = __ldg(&ecv[i]);
        accum8f(a0, __ldg(src + (size_t)p.x * 32 + lane), __uint_as_float(p.y));
        i++;
    }
    if (i + 4 <= e) {
        uint4 eAB = __ldg((const uint4*)(ecv + i));
        uint4 eCD = __ldg((const uint4*)(ecv + i + 2));
        for (; i + 8 <= e; i += 4) {
            uint4 nAB = __ldg((const uint4*)(ecv + i + 4));
            uint4 nCD = __ldg((const uint4*)(ecv + i + 6));
            uint32_t h0 = __ldg(src + (size_t)eAB.x * 32 + lane);
            uint32_t h1 = __ldg(src + (size_t)eAB.z * 32 + lane);
            uint32_t h2 = __ldg(src + (size_t)eCD.x * 32 + lane);
            uint32_t h3 = __ldg(src + (size_t)eCD.z * 32 + lane);
            accum8f(a0, h0, __uint_as_float(eAB.y));
            accum8f(a1, h1, __uint_as_float(eAB.w));
            accum8f(a0, h2, __uint_as_float(eCD.y));
            accum8f(a1, h3, __uint_as_float(eCD.w));
            eAB = nAB; eCD = nCD;
        }
        uint32_t h0 = __ldg(src + (size_t)eAB.x * 32 + lane);
        uint32_t h1 = __ldg(src + (size_t)eAB.z * 32 + lane);
        uint32_t h2 = __ldg(src + (size_t)eCD.x * 32 + lane);
        uint32_t h3 = __ldg(src + (size_t)eCD.z * 32 + lane);
        accum8f(a0, h0, __uint_as_float(eAB.y));
        accum8f(a1, h1, __uint_as_float(eAB.w));
        accum8f(a0, h2, __uint_as_float(eCD.y));
        accum8f(a1, h3, __uint_as_float(eCD.w));
        i += 4;
    }
    for (; i < e; i++) {
        uint2 p = __ldg(&ecv[i]);
        accum8f(a0, __ldg(src + (size_t)p.x * 32 + lane), __uint_as_float(p.y));
    }
    a0.x += a1.x; a0.y += a1.y; a0.z += a1.z; a0.w += a1.w;
    return a0;
}

// -------------------- Wc = Wp @ W1 (both weights, one launch) ----------------
__global__ void __launch_bounds__(128) wcomb2_kernel(
    const float* __restrict__ Wp0, const float* __restrict__ Wp1,
    const float* __restrict__ W1,
    float* __restrict__ Wc0, float* __restrict__ Wc1) {
    __shared__ float srow[D];
    const float* Wp = (blockIdx.x < 128) ? Wp0 : Wp1;
    float*       Wc = (blockIdx.x < 128) ? Wc0 : Wc1;
    int r = blockIdx.x & 127;
    srow[threadIdx.x] = Wp[r * D + threadIdx.x];
    __syncthreads();
    float acc = 0.f;
    #pragma unroll 8
    for (int k = 0; k < D; k++)
        acc += srow[k] * __ldg(&W1[k * D + threadIdx.x]);
    Wc[r * D + threadIdx.x] = acc;
}

// ------------- fused projection GEMM + bias + relu + row-normalize ----------
__global__ void __launch_bounds__(256) proj_norm_kernel(
    const float* __restrict__ x0, const float* __restrict__ x1,
    const float* __restrict__ Wc0, const float* __restrict__ Wc1,
    const float* __restrict__ bias, uint2* __restrict__ xout16) {
    __shared__ float sA[64][128];
    __shared__ float sB[32][128];

    const int nblkA = (N_A + 63) / 64;
    const float* xin;
    const float* Wc;
    int row0, nrows, base_out;
    if ((int)blockIdx.x < nblkA) {
        xin = x0; Wc = Wc0; row0 = blockIdx.x * 64; nrows = N_A; base_out = 0;
    } else {
        xin = x1; Wc = Wc1; row0 = (blockIdx.x - nblkA) * 64; nrows = N_P; base_out = N_A;
    }
    const int tid = threadIdx.x;

    #pragma unroll
    for (int i = 0; i < 8; i++) {
        int idx = tid + i * 256;
        int r   = idx >> 5;
        int k4  = idx & 31;
        float4 v = make_float4(0.f, 0.f, 0.f, 0.f);
        if (row0 + r < nrows)
            v = __ldg((const float4*)(xin + (size_t)(row0 + r) * D) + k4);
        *(float4*)&sA[r][k4 * 4] = v;
    }

    const int tr = tid >> 5;
    const int tc = tid & 31;
    float acc[8][4];
    #pragma unroll
    for (int i = 0; i < 8; i++)
        #pragma unroll
        for (int j = 0; j < 4; j++) acc[i][j] = 0.f;

    for (int kc = 0; kc < 4; kc++) {
        __syncthreads();
        #pragma unroll
        for (int i = 0; i < 4; i++) {
            int idx = tid + i * 256;
            int kk  = idx >> 5;
            int c4  = idx & 31;
            *(float4*)&sB[kk][c4 * 4] =
                __ldg((const float4*)(Wc + (size_t)(kc * 32 + kk) * D) + c4);
        }
        __syncthreads();
        #pragma unroll
        for (int kk = 0; kk < 32; kk++) {
            float4 bv = *(float4*)&sB[kk][tc * 4];
            #pragma unroll
            for (int i = 0; i < 8; i++) {
                float a = sA[tr * 8 + i][kc * 32 + kk];
                acc[i][0] += a * bv.x; acc[i][1] += a * bv.y;
                acc[i][2] += a * bv.z; acc[i][3] += a * bv.w;
            }
        }
    }

    float4 bv = __ldg((const float4*)bias + tc);
    float bb[4] = {bv.x, bv.y, bv.z, bv.w};
    #pragma unroll
    for (int i = 0; i < 8; i++)
        #pragma unroll
        for (int j = 0; j < 4; j++) {
            float v = acc[i][j] + bb[j];
            acc[i][j] = v > 0.f ? v : 0.f;
        }

    #pragma unroll
    for (int i = 0; i < 8; i++) {
        float s = acc[i][0] + acc[i][1] + acc[i][2] + acc[i][3];
        float q = acc[i][0]*acc[i][0] + acc[i][1]*acc[i][1]
                + acc[i][2]*acc[i][2] + acc[i][3]*acc[i][3];
        #pragma unroll
        for (int o = 16; o; o >>= 1) {
            s += __shfl_xor_sync(0xffffffffu, s, o);
            q += __shfl_xor_sync(0xffffffffu, q, o);
        }
        float mean = s * (1.f / 128.f);
        float var  = (q - 128.f * mean * mean) * (1.f / 127.f);
        float rstd = (var > 0.f) ? rsqrtf(var) : 0.f;
        int r = row0 + tr * 8 + i;
        if (r < nrows) {
            size_t R = (size_t)(base_out + r);
            float4 o;
            o.x = (acc[i][0] - mean) * rstd;
            o.y = (acc[i][1] - mean) * rstd;
            o.z = (acc[i][2] - mean) * rstd;
            o.w = (acc[i][3] - mean) * rstd;
            xout16[R * 32 + tc] = pack_f16x4(o);
        }
    }
}

// ------------------------------ CSR build -----------------------------------
__global__ void __launch_bounds__(256) hist2_kernel(
    const int* __restrict__ rowsA, int E1, int* __restrict__ cntA,
    const int* __restrict__ rowsP, int E2, int* __restrict__ cntP) {
    int i = blockIdx.x * 256 + threadIdx.x;
    if (i < E1) atomicAdd(&cntA[__ldg(&rowsA[i])], 1);
    if (i < E2) atomicAdd(&cntP[__ldg(&rowsP[i]) - N_A], 1);
}

__global__ void __launch_bounds__(256) scan1_kernel(
    const int* __restrict__ cntA, int nA, int* __restrict__ rpA, int* __restrict__ bsumA, int nbA,
    const int* __restrict__ cntP, int nP, int* __restrict__ rpP, int* __restrict__ bsumP) {
    __shared__ int wsum[8];
    const int* cnt; int n; int* rp; int* bsum; int blk;
    if ((int)blockIdx.x < nbA) { cnt = cntA; n = nA; rp = rpA; bsum = bsumA; blk = blockIdx.x; }
    else                       { cnt = cntP; n = nP; rp = rpP; bsum = bsumP; blk = blockIdx.x - nbA; }
    const int base = blk * 2048;
    const int t = threadIdx.x;
    int v[8]; int s = 0;
    #pragma unroll
    for (int i = 0; i < 8; i++) {
        int idx = base + t * 8 + i;
        int c = (idx < n) ? __ldg(&cnt[idx]) : 0;
        v[i] = s; s += c;
    }
    int lane = t & 31, w = t >> 5;
    int p = s;
    #pragma unroll
    for (int o = 1; o < 32; o <<= 1) {
        int q = __shfl_up_sync(0xffffffffu, p, o);
        if (lane >= o) p += q;
    }
    if (lane == 31) wsum[w] = p;
    __syncthreads();
    if (t < 8) {
        int ws = wsum[t];
        int pp = ws;
        #pragma unroll
        for (int o = 1; o < 8; o <<= 1) {
            int q = __shfl_up_sync(0xffu, pp, o);
            if (t >= o) pp += q;
        }
        wsum[t] = pp - ws;
        if (t == 7) bsum[blk] = pp;
    }
    __syncthreads();
    int texcl = (p - s) + wsum[w];
    #pragma unroll
    for (int i = 0; i < 8; i++) {
        int idx = base + t * 8 + i;
        if (idx < n) rp[idx] = texcl + v[i];
    }
}

__global__ void __launch_bounds__(256) scan2_kernel(
    int* __restrict__ bsumA, int nbA, int* __restrict__ bsumP, int nbP) {
    __shared__ int sh[256];
    int* bsum = blockIdx.x == 0 ? bsumA : bsumP;
    int nb    = blockIdx.x == 0 ? nbA   : nbP;
    int t = threadIdx.x;
    int v = (t < nb) ? bsum[t] : 0;
    sh[t] = v; __syncthreads();
    #pragma unroll
    for (int o = 1; o < 256; o <<= 1) {
        int q = (t >= o) ? sh[t - o] : 0;
        __syncthreads();
        sh[t] += q;
        __syncthreads();
    }
    if (t < nb) bsum[t] = sh[t] - v;
}

__global__ void __launch_bounds__(256) scan3_kernel(
    const int* __restrict__ bsumA, int nA, int* __restrict__ rpA, int* __restrict__ offsA,
    const int* __restrict__ cntA, int ngA,
    const int* __restrict__ bsumP, int nP, int* __restrict__ rpP, int* __restrict__ offsP,
    const int* __restrict__ cntP) {
    const int* bsum; int n; int* rp; int* offs; const int* cnt; int idx;
    if ((int)blockIdx.x < ngA) {
        bsum = bsumA; n = nA; rp = rpA; offs = offsA; cnt = cntA;
        idx = blockIdx.x * 256 + threadIdx.x;
    } else {
        bsum = bsumP; n = nP; rp = rpP; offs = offsP; cnt = cntP;
        idx = (blockIdx.x - ngA) * 256 + threadIdx.x;
    }
    if (idx < n) {
        int v = rp[idx] + __ldg(&bsum[idx >> 11]);
        rp[idx] = v;
        offs[idx] = v;
        if (idx == n - 1) rp[n] = v + __ldg(&cnt[idx]);
    }
}

// scatter + zero cnt for the next graph replay
__global__ void __launch_bounds__(256) scatter2_kernel(
    const int* __restrict__ rowsA, const int* __restrict__ colsA,
    const float* __restrict__ valsA, int E1, int* __restrict__ offsA, uint2* __restrict__ ecvA,
    int* __restrict__ cntA,
    const int* __restrict__ rowsP, const int* __restrict__ colsP,
    const float* __restrict__ valsP, int E2, int* __restrict__ offsP, uint2* __restrict__ ecvP,
    int* __restrict__ cntP) {
    int i = blockIdx.x * 256 + threadIdx.x;
    if (i < N_A) cntA[i] = 0;
    if (i < N_P) cntP[i] = 0;
    if (i < E1) {
        int r = __ldg(&rowsA[i]);
        int pos = atomicAdd(&offsA[r], 1);
        ecvA[pos] = make_uint2((unsigned)(__ldg(&colsA[i]) - N_A), __float_as_uint(__ldg(&valsA[i])));
    }
    if (i < E2) {
        int r = __ldg(&rowsP[i]) - N_A;
        int pos = atomicAdd(&offsP[r], 1);
        ecvP[pos] = make_uint2((unsigned)__ldg(&colsP[i]), __float_as_uint(__ldg(&valsP[i])));
    }
}

// --------------------- merged hop-1 SpMM (A + P in one grid) -----------------
// gathers fp16 src; writes fp16 (own-term) + fp8 (gather) planes
__global__ void __launch_bounds__(256) spmm_hop1_kernel(
    const int* __restrict__ rpA, const uint2* __restrict__ ecvA,
    const uint2* __restrict__ srcA, uint2* __restrict__ dstA16, uint32_t* __restrict__ dstA8,
    const int* __restrict__ rpP, const uint2* __restrict__ ecvP,
    const uint2* __restrict__ srcP, uint2* __restrict__ dstP16, uint32_t* __restrict__ dstP8) {
    int g = (int)((blockIdx.x * 256u + threadIdx.x) >> 5);
    if (g >= N_TOT) return;
    int lane = threadIdx.x & 31;
    const int* rp; const uint2* ecv; const uint2* src; uint2* dst16; uint32_t* dst8; int r;
    if (g < N_A) { rp = rpA; ecv = ecvA; src = srcA; dst16 = dstA16; dst8 = dstA8; r = g; }
    else         { rp = rpP; ecv = ecvP; src = srcP; dst16 = dstP16; dst8 = dstP8; r = g - N_A; }
    int s = __ldg(&rp[r]), e = __ldg(&rp[r + 1]);
    float4 a = gather16(ecv, src, s, e, lane);
    dst16[(size_t)r * 32 + lane] = pack_f16x4(a);
    float4 as = make_float4(a.x * HSCALE, a.y * HSCALE, a.z * HSCALE, a.w * HSCALE);
    dst8[(size_t)r * 32 + lane] = pack_fp8x4(as);
}

// ------------- merged pass-1 hop-2 fused with combine (A + P) ---------------
__global__ void __launch_bounds__(256) spmm_fused_kernel(
    const int* __restrict__ rpA, const uint2* __restrict__ ecvA,
    const int* __restrict__ rpP, const uint2* __restrict__ ecvP,
    const uint2* __restrict__ hA16, const uint2* __restrict__ hP16,
    const uint32_t* __restrict__ hA8, const uint32_t* __restrict__ hP8,
    const uint2* __restrict__ x16, uint2* __restrict__ res16,
    const float* __restrict__ coe) {
    int g = (int)((blockIdx.x * 256u + threadIdx.x) >> 5);
    if (g >= N_TOT) return;
    int lane = threadIdx.x & 31;
    const int* rp; const uint2* ecv; const uint32_t* hsrc8; const uint2* hown;
    int r, c_own, c_hop;
    if (g < N_A) { rp = rpA; ecv = ecvA; hsrc8 = hP8; hown = hA16; r = g;       c_own = 1; c_hop = 3; }
    else         { rp = rpP; ecv = ecvP; hsrc8 = hA8; hown = hP16; r = g - N_A; c_own = 2; c_hop = 4; }
    int s = __ldg(&rp[r]), e = __ldg(&rp[r + 1]);
    float4 w = gather8(ecv, hsrc8, s, e, lane);

    size_t R = (size_t)g;
    float c0 = __ldg(&coe[0]);
    float cw = __ldg(&coe[c_own]);
    float ch = __ldg(&coe[c_hop]) * (1.0f / HSCALE);
    float4 xv = ldg_f16x4(x16 + R * 32 + lane);
    float4 hv = ldg_f16x4(hown + (size_t)r * 32 + lane);
    float4 o;
    o.x = c0 * xv.x + cw * hv.x + ch * w.x;
    o.y = c0 * xv.y + cw * hv.y + ch * w.y;
    o.z = c0 * xv.z + cw * hv.z + ch * w.z;
    o.w = c0 * xv.w + cw * hv.w + ch * w.w;
    res16[R * 32 + lane] = pack_f16x4(o);
}

// ------ merged pass-2 hop-2 fused with combine AND output GEMM (A + P) -------
__global__ void __launch_bounds__(256) spmm_fused_out_kernel(
    const int* __restrict__ rpA, const uint2* __restrict__ ecvA,
    const int* __restrict__ rpP, const uint2* __restrict__ ecvP,
    const uint2* __restrict__ hA16, const uint2* __restrict__ hP16,
    const uint32_t* __restrict__ hA8, const uint32_t* __restrict__ hP8,
    const uint2* __restrict__ res16, float* __restrict__ out,
    const float* __restrict__ coe,
    const float* __restrict__ W2, const float* __restrict__ b2) {
    __shared__ float sW[C_OUT][D];
    __shared__ float sb2[C_OUT];
    int tid = threadIdx.x;
    for (int i = tid; i < C_OUT * D; i += 256) {
        int c = i >> 7, k = i & 127;
        sW[c][k] = __ldg(&W2[k * C_OUT + c]);
    }
    if (tid < C_OUT) sb2[tid] = __ldg(&b2[tid]);
    __syncthreads();

    int g = (int)((blockIdx.x * 256u + tid) >> 5);
    if (g >= N_TOT) return;
    int lane = tid & 31;
    const int* rp; const uint2* ecv; const uint32_t* hsrc8; const uint2* hown;
    int r, c_own, c_hop;
    if (g < N_A) { rp = rpA; ecv = ecvA; hsrc8 = hP8; hown = hA16; r = g;       c_own = 2; c_hop = 4; }
    else         { rp = rpP; ecv = ecvP; hsrc8 = hA8; hown = hP16; r = g - N_A; c_own = 1; c_hop = 3; }
    int s = __ldg(&rp[r]), e = __ldg(&rp[r + 1]);
    float4 w = gather8(ecv, hsrc8, s, e, lane);

    size_t R = (size_t)g;
    float c0 = __ldg(&coe[0]);
    float cw = __ldg(&coe[c_own]);
    float ch = __ldg(&coe[c_hop]) * (1.0f / HSCALE);
    float4 xv = ldg_f16x4(res16 + R * 32 + lane);
    float4 hv = ldg_f16x4(hown + (size_t)r * 32 + lane);
    float o0 = c0 * xv.x + cw * hv.x + ch * w.x;
    float o1 = c0 * xv.y + cw * hv.y + ch * w.y;
    float o2 = c0 * xv.z + cw * hv.z + ch * w.z;
    float o3 = c0 * xv.w + cw * hv.w + ch * w.w;

    float p[C_OUT];
    #pragma unroll
    for (int c = 0; c < C_OUT; c++) {
        float4 wv = *(const float4*)&sW[c][lane * 4];
        p[c] = o0 * wv.x + o1 * wv.y + o2 * wv.z + o3 * wv.w;
    }
    #pragma unroll
    for (int off = 16; off; off >>= 1) {
        #pragma unroll
        for (int c = 0; c < C_OUT; c++)
            p[c] += __shfl_xor_sync(0xffffffffu, p[c], off);
    }
    if (lane < C_OUT)
        out[R * C_OUT + lane] = p[lane] + sb2[lane];
}

// ----------------------------------- launch ---------------------------------
extern "C" void kernel_launch(void* const* d_in, const int* in_sizes, int n_in,
                              void* d_out, int out_size) {
    const float* x0      = (const float*)d_in[0];
    const float* x1      = (const float*)d_in[1];
    const float* vals_ap = (const float*)d_in[2];
    const float* vals_pa = (const float*)d_in[3];
    const int*   rows_ap = (const int*)  d_in[4];
    const int*   cols_ap = (const int*)  d_in[5];
    const int*   rows_pa = (const int*)  d_in[6];
    const int*   cols_pa = (const int*)  d_in[7];
    const float* Wp0     = (const float*)d_in[8];
    const float* Wp1     = (const float*)d_in[9];
    const float* W1      = (const float*)d_in[10];
    const float* b1      = (const float*)d_in[11];
    const float* W2      = (const float*)d_in[12];
    const float* b2      = (const float*)d_in[13];
    const float* coe     = (const float*)d_in[14];
    float* out = (float*)d_out;

    const int E1 = in_sizes[2];
    const int E2 = in_sizes[3];

    float *pW0c, *pW1c;
    uint2 *px16, *pres16, *phA16, *phP16, *pecvA, *pecvP;
    uint32_t *phA8, *phP8;
    int *pcntA, *pcntP, *prpA, *prpP, *poffA, *poffP, *pbA, *pbP;
    cudaGetSymbolAddress((void**)&px16,   g_x16);
    cudaGetSymbolAddress((void**)&pres16, g_res16);
    cudaGetSymbolAddress((void**)&phA16,  g_hA16);
    cudaGetSymbolAddress((void**)&phP16,  g_hP16);
    cudaGetSymbolAddress((void**)&phA8,   g_hA8);
    cudaGetSymbolAddress((void**)&phP8,   g_hP8);
    cudaGetSymbolAddress((void**)&pW0c,   g_W0c);
    cudaGetSymbolAddress((void**)&pW1c,   g_W1c);
    cudaGetSymbolAddress((void**)&pcntA,  g_cntA);
    cudaGetSymbolAddress((void**)&pcntP,  g_cntP);
    cudaGetSymbolAddress((void**)&prpA,   g_rpA);
    cudaGetSymbolAddress((void**)&prpP,   g_rpP);
    cudaGetSymbolAddress((void**)&poffA,  g_offA);
    cudaGetSymbolAddress((void**)&poffP,  g_offP);
    cudaGetSymbolAddress((void**)&pbA,    g_bsumA);
    cudaGetSymbolAddress((void**)&pbP,    g_bsumP);
    cudaGetSymbolAddress((void**)&pecvA,  g_ecvA);
    cudaGetSymbolAddress((void**)&pecvP,  g_ecvP);

    const int nbA = (N_A + 2047) / 2048;
    const int nbP = (N_P + 2047) / 2048;
    const int ngA = (N_A + 255) / 256;
    const int ngP = (N_P + 255) / 256;
    const int gT  = (int)(((size_t)N_TOT * 32 + 255) / 256);
    const int Emax = E1 > E2 ? E1 : E2;

    // 0) weight pre-combine + projection
    wcomb2_kernel<<<2 * D, D>>>(Wp0, Wp1, W1, pW0c, pW1c);
    proj_norm_kernel<<<(N_A + 63) / 64 + (N_P + 63) / 64, 256>>>(
        x0, x1, pW0c, pW1c, b1, px16);

    // 1) CSR build (3-kernel scan — fast path; cnt zeroed by scatter2)
    hist2_kernel<<<(Emax + 255) / 256, 256>>>(rows_ap, E1, pcntA, rows_pa, E2, pcntP);
    scan1_kernel<<<nbA + nbP, 256>>>(pcntA, N_A, prpA, pbA, nbA, pcntP, N_P, prpP, pbP);
    scan2_kernel<<<2, 256>>>(pbA, nbA, pbP, nbP);
    scan3_kernel<<<ngA + ngP, 256>>>(pbA, N_A, prpA, poffA, pcntA, ngA,
                                     pbP, N_P, prpP, poffP, pcntP);
    scatter2_kernel<<<(Emax + 255) / 256, 256>>>(
        rows_ap, cols_ap, vals_ap, E1, poffA, pecvA, pcntA,
        rows_pa, cols_pa, vals_pa, E2, poffP, pecvP, pcntP);

    // ---------------- pass 1 (first_order = AP, PA) ----------------
    spmm_hop1_kernel<<<gT, 256>>>(prpA, pecvA, px16 + (size_t)N_A * 32, phA16, phA8,
                                  prpP, pecvP, px16,                    phP16, phP8);
    spmm_fused_kernel<<<gT, 256>>>(prpA, pecvA, prpP, pecvP,
                                   phA16, phP16, phA8, phP8,
                                   px16, pres16, coe);

    // ---------------- pass 2 (first_order = PA, AP) ----------------
    spmm_hop1_kernel<<<gT, 256>>>(prpA, pecvA, pres16 + (size_t)N_A * 32, phA16, phA8,
                                  prpP, pecvP, pres16,                    phP16, phP8);
    spmm_fused_out_kernel<<<gT, 256>>>(prpA, pecvA, prpP, pecvP,
                                       phA16, phP16, phA8, phP8,
                                       pres16, out, coe, W2, b2);
}